// round 6
// baseline (speedup 1.0000x reference)
#include <cuda_runtime.h>

// Problem constants
#define Bsz   16
#define Lseq  4096
#define Dd    512
#define SPB   8          // d-lanes per tile
#define CH    32         // chunk length per thread
#define NCH   128        // chunks per sequence
#define NTH   1024       // SPB * NCH
#define YSTR  33         // padded per-thread stride in Y
#define WSTR  66         // padded per-seq stride for VWT/SWT
#define TILES (Bsz*(Dd/SPB))   // 1024

// smem floats: Y + RR + PW(16) + PK(8) + VWT + SWT + XEa + XEb + CV
#define SMEM_FLOATS (NTH*YSTR + 2*CH + 16 + 8 + 8*WSTR + 8*WSTR + 2*NTH + 2*NTH + 16)

__global__ void __launch_bounds__(NTH, 1)
iir_filtfilt_kernel(const float* __restrict__ x,
                    const float* __restrict__ bc,
                    const float* __restrict__ am,
                    float* __restrict__ out)
{
    extern __shared__ float sm[];
    float*  Y   = sm;                               // NTH*YSTR : x copy (private/thread)
    float2* RR  = (float2*)(Y + NTH * YSTR);        // CH : row0(A^(i+1))
    float*  PW  = (float*)(RR + CH);                // 16 : A^32,A^64,A^96,A^128
    float*  PK  = PW + 16;                          // 8  : A^256, A^512
    float*  VWT = PK + 8;                           // 8*WSTR : warp aggregates [seq][w]
    float*  SWT = VWT + 8 * WSTR;                   // 8*WSTR : warp start states
    float*  XEa = SWT + 8 * WSTR;                   // 2*NTH : x halos
    float*  XEb = XEa + 2 * NTH;                    // 2*NTH : y edges
    float*  CV  = XEb + 2 * NTH;                    // 16 : boundary constants

    const int tid  = threadIdx.x;
    const int lane = tid & 31;
    const int wrp  = tid >> 5;                      // 0..31
    const int seq  = tid & 7;
    const int ch   = tid >> 3;                      // 0..127
    const int g    = lane >> 3;                     // chunk-in-warp 0..3

    const float b0  = bc[0], b1 = bc[1], b2 = bc[2];
    const float na1 = am[0], na2 = am[1];           // A row0 = (-a1,-a2)
    const float bsum = b0 + b1 + b2;

    // Thread 0: RR[i]=row0(A^(i+1)); PW = {A^32,A^64,A^96,A^128}; PK = {A^256,A^512}.
    if (tid == 0) {
        float p00 = na1, p01 = na2, p10 = 1.f, p11 = 0.f;
        RR[0] = make_float2(p00, p01);
        for (int i = 1; i < CH; ++i) {
            float q00 = fmaf(na1, p00, na2 * p10);
            float q01 = fmaf(na1, p01, na2 * p11);
            p10 = p00; p11 = p01; p00 = q00; p01 = q01;
            RR[i] = make_float2(p00, p01);
        }
        float a00 = p00, a01 = p01, a10 = p10, a11 = p11;   // A^32
        float c00 = a00, c01 = a01, c10 = a10, c11 = a11;
        PW[0] = c00; PW[1] = c01; PW[2] = c10; PW[3] = c11;
        for (int k = 1; k < 4; ++k) {
            float n00 = c00*a00 + c01*a10, n01 = c00*a01 + c01*a11;
            float n10 = c10*a00 + c11*a10, n11 = c10*a01 + c11*a11;
            c00 = n00; c01 = n01; c10 = n10; c11 = n11;
            PW[4*k] = c00; PW[4*k+1] = c01; PW[4*k+2] = c10; PW[4*k+3] = c11;
        }
        // c = A^128; square twice.
        float d00 = c00*c00 + c01*c10, d01 = c00*c01 + c01*c11;
        float d10 = c10*c00 + c11*c10, d11 = c10*c01 + c11*c11;   // A^256
        PK[0] = d00; PK[1] = d01; PK[2] = d10; PK[3] = d11;
        float e00 = d00*d00 + d01*d10, e01 = d00*d01 + d01*d11;
        float e10 = d10*d00 + d11*d10, e11 = d10*d01 + d11*d11;   // A^512
        PK[4] = e00; PK[5] = e01; PK[6] = e10; PK[7] = e11;
    }

    const size_t OUTT = (size_t)Bsz * Lseq * Dd;

    // Preload first tile into registers.
    float xr[CH];
    {
        int tf = blockIdx.x;
        const float* xp = x + ((size_t)(tf >> 6) * Lseq + (size_t)ch * CH) * Dd
                            + ((tf & 63) * SPB) + seq;
        #pragma unroll
        for (int i = 0; i < CH; ++i) xr[i] = xp[(size_t)i * Dd];
    }

    for (int t = blockIdx.x; t < TILES; t += gridDim.x) {
        const int b  = t >> 6;
        const int d0 = (t & 63) * SPB;

        // Tile top: private x copy + halo publish (safe: prior readers are
        // multiple barriers in the past).
        #pragma unroll
        for (int i = 0; i < CH; ++i) Y[tid * YSTR + i] = xr[i];
        XEa[2 * tid]     = xr[CH - 2];
        XEa[2 * tid + 1] = xr[CH - 1];
        if (ch == 0) CV[seq] = bsum * xr[0];
        __syncthreads();    // B1: halos + CV visible

        // Deduped L2 prefetch of next tile (one request per 32B sector).
        int tn = t + gridDim.x;  if (tn >= TILES) tn = t;
        const float* xpn = x + ((size_t)(tn >> 6) * Lseq + (size_t)ch * CH) * Dd
                             + ((tn & 63) * SPB) + seq;
        #pragma unroll
        for (int k = 0; k < 4; ++k)
            asm volatile("prefetch.global.L2 [%0];"
                         :: "l"(xpn + (size_t)(8 * k + seq) * Dd));

        // ---------------- forward zero-init scan (p0 -> xr) ------------------
        float xm1, xm2;
        if (ch == 0) { xm1 = xr[0]; xm2 = xr[0]; }
        else         { xm1 = XEa[2*(tid-SPB)+1]; xm2 = XEa[2*(tid-SPB)]; }
        float s0 = 0.f, s1 = 0.f;
        #pragma unroll
        for (int i = 0; i < CH; ++i) {
            float bx = fmaf(b2, xm2, fmaf(b1, xm1, b0 * xr[i]));
            xm2 = xm1; xm1 = xr[i];
            float ns = fmaf(na1, s0, fmaf(na2, s1, bx));
            s1 = s0; s0 = ns;
            xr[i] = ns;
        }

        // Intra-warp aggregate over the warp's 4 chunks per sequence.
        float va0 = __shfl_up_sync(0xffffffffu, s0, 8);
        float va1 = __shfl_up_sync(0xffffffffu, s1, 8);
        float vb0 = __shfl_up_sync(0xffffffffu, s0, 16);
        float vb1 = __shfl_up_sync(0xffffffffu, s1, 16);
        float vc0 = __shfl_up_sync(0xffffffffu, s0, 24);
        float vc1 = __shfl_up_sync(0xffffffffu, s1, 24);
        if (g < 1) { va0 = 0.f; va1 = 0.f; }
        if (g < 2) { vb0 = 0.f; vb1 = 0.f; }
        if (g < 3) { vc0 = 0.f; vc1 = 0.f; }
        float E0, E1;
        {
            float m00 = PW[0], m01 = PW[1], m10 = PW[2], m11 = PW[3];   // A^32
            float w00 = PW[4], w01 = PW[5], w10 = PW[6], w11 = PW[7];   // A^64
            E0 = va0 + m00*vb0 + m01*vb1 + w00*vc0 + w01*vc1;
            E1 = va1 + m10*vb0 + m11*vb1 + w10*vc0 + w11*vc1;
            if (g == 3) {
                VWT[seq * WSTR + 2 * wrp]     = fmaf(m00, E0, fmaf(m01, E1, s0));
                VWT[seq * WSTR + 2 * wrp + 1] = fmaf(m10, E0, fmaf(m11, E1, s1));
            }
        }
        __syncthreads();    // B2

        // Kogge-Stone combine over 32 warp aggregates: warp s handles seq s.
        // Shifts 1,2,4 with M=A^128, A^256, A^512 (shift>=8 terms ~1e-41: drop).
        if (wrp < 8) {
            int s = wrp;
            float2 vv = *(float2*)&VWT[s * WSTR + 2 * lane];
            float v0 = vv.x, v1 = vv.y;
            float m00 = PW[12], m01 = PW[13], m10 = PW[14], m11 = PW[15];  // A^128
            float c = CV[s];
            if (lane == 0) {
                v0 = fmaf(m00 + m01, c, v0);
                v1 = fmaf(m10 + m11, c, v1);
            }
            float u0 = __shfl_up_sync(0xffffffffu, v0, 1);
            float u1 = __shfl_up_sync(0xffffffffu, v1, 1);
            if (lane >= 1) { v0 = fmaf(m00,u0,fmaf(m01,u1,v0)); v1 = fmaf(m10,u0,fmaf(m11,u1,v1)); }
            u0 = __shfl_up_sync(0xffffffffu, v0, 2);
            u1 = __shfl_up_sync(0xffffffffu, v1, 2);
            if (lane >= 2) { v0 = fmaf(PK[0],u0,fmaf(PK[1],u1,v0)); v1 = fmaf(PK[2],u0,fmaf(PK[3],u1,v1)); }
            u0 = __shfl_up_sync(0xffffffffu, v0, 4);
            u1 = __shfl_up_sync(0xffffffffu, v1, 4);
            if (lane >= 4) { v0 = fmaf(PK[4],u0,fmaf(PK[5],u1,v0)); v1 = fmaf(PK[6],u0,fmaf(PK[7],u1,v1)); }
            float t0v = __shfl_up_sync(0xffffffffu, v0, 1);
            float t1v = __shfl_up_sync(0xffffffffu, v1, 1);
            if (lane == 0) { t0v = c; t1v = c; }
            SWT[s * WSTR + 2 * lane]     = t0v;
            SWT[s * WSTR + 2 * lane + 1] = t1v;
        }
        __syncthreads();    // B3

        // Forward start state: ss = A^(32g) * T_w + E_g ; publish y-edges.
        float ss0, ss1;
        {
            float T0 = SWT[seq * WSTR + 2 * wrp], T1 = SWT[seq * WSTR + 2 * wrp + 1];
            if (g == 0) { ss0 = T0; ss1 = T1; }
            else {
                const float* P = PW + 4 * (g - 1);
                ss0 = fmaf(P[0], T0, fmaf(P[1], T1, E0));
                ss1 = fmaf(P[2], T0, fmaf(P[3], T1, E1));
            }
        }
        {
            float2 r0 = RR[0], r1 = RR[1];
            XEb[2 * tid]     = fmaf(r0.x, ss0, fmaf(r0.y, ss1, xr[0]));
            XEb[2 * tid + 1] = fmaf(r1.x, ss0, fmaf(r1.y, ss1, xr[1]));
            if (ch == NCH - 1) {
                float2 rl = RR[CH - 1];
                CV[SPB + seq] = bsum * fmaf(rl.x, ss0, fmaf(rl.y, ss1, xr[CH - 1]));
            }
        }
        __syncthreads();    // B4

        // ---------------- backward zero-init scan (p0_bwd -> xr) -------------
        float yp1, yp2;
        if (ch == NCH - 1) {
            float2 rl = RR[CH - 1];
            float e = fmaf(rl.x, ss0, fmaf(rl.y, ss1, xr[CH - 1]));
            yp1 = e; yp2 = e;
        } else {
            yp1 = XEb[2 * (tid + SPB)];
            yp2 = XEb[2 * (tid + SPB) + 1];
        }
        s0 = 0.f; s1 = 0.f;
        #pragma unroll
        for (int i = CH - 1; i >= 0; --i) {
            float2 r = RR[i];
            float yv = fmaf(r.x, ss0, fmaf(r.y, ss1, xr[i]));
            float bx = fmaf(b2, yp2, fmaf(b1, yp1, b0 * yv));
            yp2 = yp1; yp1 = yv;
            float ns = fmaf(na1, s0, fmaf(na2, s1, bx));
            s1 = s0; s0 = ns;
            xr[i] = ns;
        }

        // Backward intra-warp aggregate (descending chunk order).
        va0 = __shfl_down_sync(0xffffffffu, s0, 8);
        va1 = __shfl_down_sync(0xffffffffu, s1, 8);
        vb0 = __shfl_down_sync(0xffffffffu, s0, 16);
        vb1 = __shfl_down_sync(0xffffffffu, s1, 16);
        vc0 = __shfl_down_sync(0xffffffffu, s0, 24);
        vc1 = __shfl_down_sync(0xffffffffu, s1, 24);
        if (g > 2) { va0 = 0.f; va1 = 0.f; }
        if (g > 1) { vb0 = 0.f; vb1 = 0.f; }
        if (g > 0) { vc0 = 0.f; vc1 = 0.f; }
        {
            float m00 = PW[0], m01 = PW[1], m10 = PW[2], m11 = PW[3];
            float w00 = PW[4], w01 = PW[5], w10 = PW[6], w11 = PW[7];
            E0 = va0 + m00*vb0 + m01*vb1 + w00*vc0 + w01*vc1;
            E1 = va1 + m10*vb0 + m11*vb1 + w10*vc0 + w11*vc1;
            if (g == 0) {
                VWT[seq * WSTR + 2 * wrp]     = fmaf(m00, E0, fmaf(m01, E1, s0));
                VWT[seq * WSTR + 2 * wrp + 1] = fmaf(m10, E0, fmaf(m11, E1, s1));
            }
        }
        __syncthreads();    // B5

        // Kogge-Stone backward combine (mirror, shfl_down).
        if (wrp < 8) {
            int s = wrp;
            float2 vv = *(float2*)&VWT[s * WSTR + 2 * lane];
            float v0 = vv.x, v1 = vv.y;
            float m00 = PW[12], m01 = PW[13], m10 = PW[14], m11 = PW[15];
            float c = CV[SPB + s];
            if (lane == 31) {
                v0 = fmaf(m00 + m01, c, v0);
                v1 = fmaf(m10 + m11, c, v1);
            }
            float u0 = __shfl_down_sync(0xffffffffu, v0, 1);
            float u1 = __shfl_down_sync(0xffffffffu, v1, 1);
            if (lane <= 30) { v0 = fmaf(m00,u0,fmaf(m01,u1,v0)); v1 = fmaf(m10,u0,fmaf(m11,u1,v1)); }
            u0 = __shfl_down_sync(0xffffffffu, v0, 2);
            u1 = __shfl_down_sync(0xffffffffu, v1, 2);
            if (lane <= 29) { v0 = fmaf(PK[0],u0,fmaf(PK[1],u1,v0)); v1 = fmaf(PK[2],u0,fmaf(PK[3],u1,v1)); }
            u0 = __shfl_down_sync(0xffffffffu, v0, 4);
            u1 = __shfl_down_sync(0xffffffffu, v1, 4);
            if (lane <= 27) { v0 = fmaf(PK[4],u0,fmaf(PK[5],u1,v0)); v1 = fmaf(PK[6],u0,fmaf(PK[7],u1,v1)); }
            float t0v = __shfl_down_sync(0xffffffffu, v0, 1);
            float t1v = __shfl_down_sync(0xffffffffu, v1, 1);
            if (lane == 31) { t0v = c; t1v = c; }
            SWT[s * WSTR + 2 * lane]     = t0v;
            SWT[s * WSTR + 2 * lane + 1] = t1v;
        }
        __syncthreads();    // B6

        // Backward start state: sb = A^(32(3-g)) * T'_w + E'_g.
        float sb0, sb1;
        {
            float T0 = SWT[seq * WSTR + 2 * wrp], T1 = SWT[seq * WSTR + 2 * wrp + 1];
            if (g == 3) { sb0 = T0; sb1 = T1; }
            else {
                const float* P = PW + 4 * (2 - g);
                sb0 = fmaf(P[0], T0, fmaf(P[1], T1, E0));
                sb1 = fmaf(P[2], T0, fmaf(P[3], T1, E1));
            }
        }

        // Final fix-up + streaming stores, with next tile's x loads pipelined
        // into xr[i] right after its last read.
        float* os = out + ((size_t)b * Lseq + (size_t)ch * CH) * Dd + d0 + seq;
        float* ot = os + OUTT;
        #pragma unroll
        for (int i = 0; i < CH; ++i) {
            float2 r = RR[CH - 1 - i];
            float se = fmaf(r.x, sb0, fmaf(r.y, sb1, xr[i]));
            float nx = xpn[(size_t)i * Dd];          // L2-hot (prefetched)
            __stcs(os + (size_t)i * Dd, se);
            __stcs(ot + (size_t)i * Dd, Y[tid * YSTR + i] - se);
            xr[i] = nx;
        }
    }
}

extern "C" void kernel_launch(void* const* d_in, const int* in_sizes, int n_in,
                              void* d_out, int out_size)
{
    const float* x  = (const float*)d_in[0];
    const float* bc = (const float*)d_in[1];
    const float* am = (const float*)d_in[2];
    float* out = (float*)d_out;

    int dev = 0;
    cudaGetDevice(&dev);
    int sms = 148;
    cudaDeviceGetAttribute(&sms, cudaDevAttrMultiProcessorCount, dev);
    if (sms > TILES) sms = TILES;

    const size_t smem = (size_t)SMEM_FLOATS * sizeof(float);   // ~153 KB
    cudaFuncSetAttribute(iir_filtfilt_kernel,
                         cudaFuncAttributeMaxDynamicSharedMemorySize, (int)smem);

    iir_filtfilt_kernel<<<sms, NTH, smem>>>(x, bc, am, out);
}

// round 7
// speedup vs baseline: 1.1522x; 1.1522x over previous
#include <cuda_runtime.h>

// Problem constants
#define Bsz   16
#define Lseq  4096
#define Dd    512
#define SPB   8          // d-lanes per tile
#define CH    32         // chunk length per thread
#define NCH   128        // chunks per sequence
#define NTH   1024       // SPB * NCH
#define YSTR  33         // padded per-thread stride in Y
#define WSTR  66         // padded per-seq stride for VWT/SWT
#define TILES (Bsz*(Dd/SPB))   // 1024

// smem floats: Y + RR + PW(16) + PK(8) + VWT + SWT + XE + CV
#define SMEM_FLOATS (NTH*YSTR + 2*CH + 16 + 8 + 8*WSTR + 8*WSTR + 2*NTH + 16)

__global__ void __launch_bounds__(NTH, 1)
iir_filtfilt_kernel(const float* __restrict__ x,
                    const float* __restrict__ bc,
                    const float* __restrict__ am,
                    float* __restrict__ out)
{
    extern __shared__ float sm[];
    float*  Y   = sm;                               // NTH*YSTR : x copy (for trend)
    float2* RR  = (float2*)(Y + NTH * YSTR);        // CH : row0(A^(i+1))
    float*  PW  = (float*)(RR + CH);                // 16 : A^32,A^64,A^96,A^128
    float*  PK  = PW + 16;                          // 8  : A^256, A^512
    float*  VWT = PK + 8;                           // 8*WSTR : warp aggregates [seq][w]
    float*  SWT = VWT + 8 * WSTR;                   // 8*WSTR : warp start states
    float*  XE  = SWT + 8 * WSTR;                   // 2*NTH : x-halos then y-edges
    float*  CV  = XE + 2 * NTH;                     // 16 : boundary constants

    const int tid  = threadIdx.x;
    const int lane = tid & 31;
    const int wrp  = tid >> 5;                      // 0..31
    const int seq  = tid & 7;
    const int ch   = tid >> 3;                      // 0..127
    const int g    = lane >> 3;                     // chunk-in-warp 0..3

    const float b0  = bc[0], b1 = bc[1], b2 = bc[2];
    const float na1 = am[0], na2 = am[1];           // A row0 = (-a1,-a2)
    const float bsum = b0 + b1 + b2;

    // Thread 0: RR[i]=row0(A^(i+1)); PW = {A^32,A^64,A^96,A^128}; PK = {A^256,A^512}.
    if (tid == 0) {
        float p00 = na1, p01 = na2, p10 = 1.f, p11 = 0.f;
        RR[0] = make_float2(p00, p01);
        for (int i = 1; i < CH; ++i) {
            float q00 = fmaf(na1, p00, na2 * p10);
            float q01 = fmaf(na1, p01, na2 * p11);
            p10 = p00; p11 = p01; p00 = q00; p01 = q01;
            RR[i] = make_float2(p00, p01);
        }
        float a00 = p00, a01 = p01, a10 = p10, a11 = p11;   // A^32
        float c00 = a00, c01 = a01, c10 = a10, c11 = a11;
        PW[0] = c00; PW[1] = c01; PW[2] = c10; PW[3] = c11;
        for (int k = 1; k < 4; ++k) {
            float n00 = c00*a00 + c01*a10, n01 = c00*a01 + c01*a11;
            float n10 = c10*a00 + c11*a10, n11 = c10*a01 + c11*a11;
            c00 = n00; c01 = n01; c10 = n10; c11 = n11;
            PW[4*k] = c00; PW[4*k+1] = c01; PW[4*k+2] = c10; PW[4*k+3] = c11;
        }
        float d00 = c00*c00 + c01*c10, d01 = c00*c01 + c01*c11;
        float d10 = c10*c00 + c11*c10, d11 = c10*c01 + c11*c11;   // A^256
        PK[0] = d00; PK[1] = d01; PK[2] = d10; PK[3] = d11;
        float e00 = d00*d00 + d01*d10, e01 = d00*d01 + d01*d11;
        float e10 = d10*d00 + d11*d10, e11 = d10*d01 + d11*d11;   // A^512
        PK[4] = e00; PK[5] = e01; PK[6] = e10; PK[7] = e11;
    }

    const size_t OUTT = (size_t)Bsz * Lseq * Dd;

    for (int t = blockIdx.x; t < TILES; t += gridDim.x) {
        const int b  = t >> 6;
        const int d0 = (t & 63) * SPB;
        const float* xp = x + ((size_t)b * Lseq + (size_t)ch * CH) * Dd + d0 + seq;

        // Load own chunk to registers (front-batched; L2-hot after first tile).
        float xr[CH];
        #pragma unroll
        for (int i = 0; i < CH; ++i) xr[i] = xp[(size_t)i * Dd];

        __syncthreads();    // B1: previous tile finished reading Y/XE/CV

        #pragma unroll
        for (int i = 0; i < CH; ++i) Y[tid * YSTR + i] = xr[i];
        XE[2 * tid]     = xr[CH - 2];
        XE[2 * tid + 1] = xr[CH - 1];
        if (ch == 0) CV[seq] = bsum * xr[0];
        __syncthreads();    // B2

        // Next-tile prefetch target (self-prefetch on last tile: harmless).
        int t2 = t + gridDim.x;  if (t2 >= TILES) t2 = t;
        const float* xpn = x + ((size_t)(t2 >> 6) * Lseq + (size_t)ch * CH) * Dd
                             + ((t2 & 63) * SPB) + seq;

        // ---------------- forward zero-init scan (p0 -> xr) ------------------
        float xm1, xm2;
        if (ch == 0) { xm1 = xr[0]; xm2 = xr[0]; }
        else         { xm1 = XE[2*(tid-SPB)+1]; xm2 = XE[2*(tid-SPB)]; }
        float s0 = 0.f, s1 = 0.f;
        #pragma unroll
        for (int i = 0; i < CH; ++i) {
            asm volatile("prefetch.global.L2 [%0];" :: "l"(xpn + (size_t)i * Dd));
            float bx = fmaf(b2, xm2, fmaf(b1, xm1, b0 * xr[i]));
            xm2 = xm1; xm1 = xr[i];
            float ns = fmaf(na1, s0, fmaf(na2, s1, bx));
            s1 = s0; s0 = ns;
            xr[i] = ns;
        }

        // Intra-warp aggregate over the warp's 4 chunks per sequence.
        float va0 = __shfl_up_sync(0xffffffffu, s0, 8);
        float va1 = __shfl_up_sync(0xffffffffu, s1, 8);
        float vb0 = __shfl_up_sync(0xffffffffu, s0, 16);
        float vb1 = __shfl_up_sync(0xffffffffu, s1, 16);
        float vc0 = __shfl_up_sync(0xffffffffu, s0, 24);
        float vc1 = __shfl_up_sync(0xffffffffu, s1, 24);
        if (g < 1) { va0 = 0.f; va1 = 0.f; }
        if (g < 2) { vb0 = 0.f; vb1 = 0.f; }
        if (g < 3) { vc0 = 0.f; vc1 = 0.f; }
        float E0, E1;
        {
            float m00 = PW[0], m01 = PW[1], m10 = PW[2], m11 = PW[3];   // A^32
            float w00 = PW[4], w01 = PW[5], w10 = PW[6], w11 = PW[7];   // A^64
            E0 = va0 + m00*vb0 + m01*vb1 + w00*vc0 + w01*vc1;
            E1 = va1 + m10*vb0 + m11*vb1 + w10*vc0 + w11*vc1;
            if (g == 3) {
                VWT[seq * WSTR + 2 * wrp]     = fmaf(m00, E0, fmaf(m01, E1, s0));
                VWT[seq * WSTR + 2 * wrp + 1] = fmaf(m10, E0, fmaf(m11, E1, s1));
            }
        }
        __syncthreads();    // B3

        // Kogge-Stone combine over 32 warp aggregates (warp s = sequence s).
        // Shifts 1,2,4 with A^128, A^256, A^512; shift>=8 terms ~1e-42: dropped.
        if (wrp < 8) {
            int s = wrp;
            float2 vv = *(float2*)&VWT[s * WSTR + 2 * lane];
            float v0 = vv.x, v1 = vv.y;
            float m00 = PW[12], m01 = PW[13], m10 = PW[14], m11 = PW[15];  // A^128
            float c = CV[s];
            if (lane == 0) {
                v0 = fmaf(m00 + m01, c, v0);
                v1 = fmaf(m10 + m11, c, v1);
            }
            float u0 = __shfl_up_sync(0xffffffffu, v0, 1);
            float u1 = __shfl_up_sync(0xffffffffu, v1, 1);
            if (lane >= 1) { v0 = fmaf(m00,u0,fmaf(m01,u1,v0)); v1 = fmaf(m10,u0,fmaf(m11,u1,v1)); }
            u0 = __shfl_up_sync(0xffffffffu, v0, 2);
            u1 = __shfl_up_sync(0xffffffffu, v1, 2);
            if (lane >= 2) { v0 = fmaf(PK[0],u0,fmaf(PK[1],u1,v0)); v1 = fmaf(PK[2],u0,fmaf(PK[3],u1,v1)); }
            u0 = __shfl_up_sync(0xffffffffu, v0, 4);
            u1 = __shfl_up_sync(0xffffffffu, v1, 4);
            if (lane >= 4) { v0 = fmaf(PK[4],u0,fmaf(PK[5],u1,v0)); v1 = fmaf(PK[6],u0,fmaf(PK[7],u1,v1)); }
            float t0v = __shfl_up_sync(0xffffffffu, v0, 1);
            float t1v = __shfl_up_sync(0xffffffffu, v1, 1);
            if (lane == 0) { t0v = c; t1v = c; }
            SWT[s * WSTR + 2 * lane]     = t0v;
            SWT[s * WSTR + 2 * lane + 1] = t1v;
        }
        __syncthreads();    // B4

        // Forward start state: ss = A^(32g) * T_w + E_g ; publish y-edges.
        float ss0, ss1;
        {
            float T0 = SWT[seq * WSTR + 2 * wrp], T1 = SWT[seq * WSTR + 2 * wrp + 1];
            if (g == 0) { ss0 = T0; ss1 = T1; }
            else {
                const float* P = PW + 4 * (g - 1);
                ss0 = fmaf(P[0], T0, fmaf(P[1], T1, E0));
                ss1 = fmaf(P[2], T0, fmaf(P[3], T1, E1));
            }
        }
        {
            float2 r0 = RR[0], r1 = RR[1];
            XE[2 * tid]     = fmaf(r0.x, ss0, fmaf(r0.y, ss1, xr[0]));
            XE[2 * tid + 1] = fmaf(r1.x, ss0, fmaf(r1.y, ss1, xr[1]));
            if (ch == NCH - 1) {
                float2 rl = RR[CH - 1];
                CV[SPB + seq] = bsum * fmaf(rl.x, ss0, fmaf(rl.y, ss1, xr[CH - 1]));
            }
        }
        __syncthreads();    // B5

        // ---------------- backward zero-init scan (p0_bwd -> xr) -------------
        float yp1, yp2;
        if (ch == NCH - 1) {
            float2 rl = RR[CH - 1];
            float e = fmaf(rl.x, ss0, fmaf(rl.y, ss1, xr[CH - 1]));
            yp1 = e; yp2 = e;
        } else {
            yp1 = XE[2 * (tid + SPB)];
            yp2 = XE[2 * (tid + SPB) + 1];
        }
        s0 = 0.f; s1 = 0.f;
        #pragma unroll
        for (int i = CH - 1; i >= 0; --i) {
            float2 r = RR[i];
            float yv = fmaf(r.x, ss0, fmaf(r.y, ss1, xr[i]));
            float bx = fmaf(b2, yp2, fmaf(b1, yp1, b0 * yv));
            yp2 = yp1; yp1 = yv;
            float ns = fmaf(na1, s0, fmaf(na2, s1, bx));
            s1 = s0; s0 = ns;
            xr[i] = ns;
        }

        // Backward intra-warp aggregate (descending chunk order).
        va0 = __shfl_down_sync(0xffffffffu, s0, 8);
        va1 = __shfl_down_sync(0xffffffffu, s1, 8);
        vb0 = __shfl_down_sync(0xffffffffu, s0, 16);
        vb1 = __shfl_down_sync(0xffffffffu, s1, 16);
        vc0 = __shfl_down_sync(0xffffffffu, s0, 24);
        vc1 = __shfl_down_sync(0xffffffffu, s1, 24);
        if (g > 2) { va0 = 0.f; va1 = 0.f; }
        if (g > 1) { vb0 = 0.f; vb1 = 0.f; }
        if (g > 0) { vc0 = 0.f; vc1 = 0.f; }
        {
            float m00 = PW[0], m01 = PW[1], m10 = PW[2], m11 = PW[3];
            float w00 = PW[4], w01 = PW[5], w10 = PW[6], w11 = PW[7];
            E0 = va0 + m00*vb0 + m01*vb1 + w00*vc0 + w01*vc1;
            E1 = va1 + m10*vb0 + m11*vb1 + w10*vc0 + w11*vc1;
            if (g == 0) {
                VWT[seq * WSTR + 2 * wrp]     = fmaf(m00, E0, fmaf(m01, E1, s0));
                VWT[seq * WSTR + 2 * wrp + 1] = fmaf(m10, E0, fmaf(m11, E1, s1));
            }
        }
        __syncthreads();    // B6

        // Kogge-Stone backward combine (mirror, shfl_down).
        if (wrp < 8) {
            int s = wrp;
            float2 vv = *(float2*)&VWT[s * WSTR + 2 * lane];
            float v0 = vv.x, v1 = vv.y;
            float m00 = PW[12], m01 = PW[13], m10 = PW[14], m11 = PW[15];
            float c = CV[SPB + s];
            if (lane == 31) {
                v0 = fmaf(m00 + m01, c, v0);
                v1 = fmaf(m10 + m11, c, v1);
            }
            float u0 = __shfl_down_sync(0xffffffffu, v0, 1);
            float u1 = __shfl_down_sync(0xffffffffu, v1, 1);
            if (lane <= 30) { v0 = fmaf(m00,u0,fmaf(m01,u1,v0)); v1 = fmaf(m10,u0,fmaf(m11,u1,v1)); }
            u0 = __shfl_down_sync(0xffffffffu, v0, 2);
            u1 = __shfl_down_sync(0xffffffffu, v1, 2);
            if (lane <= 29) { v0 = fmaf(PK[0],u0,fmaf(PK[1],u1,v0)); v1 = fmaf(PK[2],u0,fmaf(PK[3],u1,v1)); }
            u0 = __shfl_down_sync(0xffffffffu, v0, 4);
            u1 = __shfl_down_sync(0xffffffffu, v1, 4);
            if (lane <= 27) { v0 = fmaf(PK[4],u0,fmaf(PK[5],u1,v0)); v1 = fmaf(PK[6],u0,fmaf(PK[7],u1,v1)); }
            float t0v = __shfl_down_sync(0xffffffffu, v0, 1);
            float t1v = __shfl_down_sync(0xffffffffu, v1, 1);
            if (lane == 31) { t0v = c; t1v = c; }
            SWT[s * WSTR + 2 * lane]     = t0v;
            SWT[s * WSTR + 2 * lane + 1] = t1v;
        }
        __syncthreads();    // B7

        // Backward start state: sb = A^(32(3-g)) * T'_w + E'_g.
        float sb0, sb1;
        {
            float T0 = SWT[seq * WSTR + 2 * wrp], T1 = SWT[seq * WSTR + 2 * wrp + 1];
            if (g == 3) { sb0 = T0; sb1 = T1; }
            else {
                const float* P = PW + 4 * (2 - g);
                sb0 = fmaf(P[0], T0, fmaf(P[1], T1, E0));
                sb1 = fmaf(P[2], T0, fmaf(P[3], T1, E1));
            }
        }

        // Final fix-up + streaming stores (store-only drain, as in R5).
        float* os = out + ((size_t)b * Lseq + (size_t)ch * CH) * Dd + d0 + seq;
        float* ot = os + OUTT;
        #pragma unroll
        for (int i = 0; i < CH; ++i) {
            float2 r = RR[CH - 1 - i];
            float se = fmaf(r.x, sb0, fmaf(r.y, sb1, xr[i]));
            __stcs(os + (size_t)i * Dd, se);
            __stcs(ot + (size_t)i * Dd, Y[tid * YSTR + i] - se);
        }
    }
}

extern "C" void kernel_launch(void* const* d_in, const int* in_sizes, int n_in,
                              void* d_out, int out_size)
{
    const float* x  = (const float*)d_in[0];
    const float* bc = (const float*)d_in[1];
    const float* am = (const float*)d_in[2];
    float* out = (float*)d_out;

    int dev = 0;
    cudaGetDevice(&dev);
    int sms = 148;
    cudaDeviceGetAttribute(&sms, cudaDevAttrMultiProcessorCount, dev);
    if (sms > TILES) sms = TILES;

    const size_t smem = (size_t)SMEM_FLOATS * sizeof(float);   // ~146 KB
    cudaFuncSetAttribute(iir_filtfilt_kernel,
                         cudaFuncAttributeMaxDynamicSharedMemorySize, (int)smem);

    iir_filtfilt_kernel<<<sms, NTH, smem>>>(x, bc, am, out);
}